// round 1
// baseline (speedup 1.0000x reference)
#include <cuda_runtime.h>
#include <cuda_bf16.h>
#include <cstdint>

// Problem constants
#define BB    2048
#define F1N   10
#define F2N   25
#define DD    128
#define NTOK  261          // 1 + F1 + F1*F2
#define HH    256
#define D4    32           // float4 per 128-float row
#define MROWS (BB * 11)    // 22528 rows into GEMM1

// Scratch (device globals: allocation-free)
__device__ __align__(16) float g_A1[MROWS * HH];   // [b*11+r][256]  GEMM1 input
__device__ __align__(16) float g_H1[MROWS * HH];   // GEMM1 output
__device__ __align__(16) float g_A2[BB * 2 * HH];  // [b][512]       GEMM2 input

// ---------------- f32x2 packed-FMA helpers (FFMA2 path) ----------------
__device__ __forceinline__ unsigned long long dup2(float a) {
    unsigned long long r;
    asm("mov.b64 %0, {%1, %1};" : "=l"(r) : "f"(a));
    return r;
}
__device__ __forceinline__ void fma2(unsigned long long& acc,
                                     unsigned long long a,
                                     unsigned long long b) {
    asm("fma.rn.f32x2 %0, %1, %2, %0;" : "+l"(acc) : "l"(a), "l"(b));
}
__device__ __forceinline__ float2 unpk2(unsigned long long v) {
    float2 f;
    asm("mov.b64 {%0, %1}, %2;" : "=f"(f.x), "=f"(f.y) : "l"(v));
    return f;
}

// ---------------- K1: neighbor-mean reduction, builds A1 ----------------
// A1[b][0]   = [ seed | mean(hop1) ]
// A1[b][1+f] = [ hop1_f | mean(hop2_f) ]
__global__ void k_reduce(const float4* __restrict__ x4) {
    const int HOP2_SLOTS = BB * F1N * D4;  // 655360
    int idx = blockIdx.x * blockDim.x + threadIdx.x;
    float4* A14 = reinterpret_cast<float4*>(g_A1);

    if (idx < HOP2_SLOTS) {
        // one (b, f, d4) slot: mean over 25 hop2 rows; warp covers one full row (coalesced)
        int d4 = idx & 31;
        int fg = idx >> 5;
        int f = fg % F1N;
        int b = fg / F1N;
        const float4* p = x4 + (size_t)b * NTOK * D4 + (size_t)(1 + F1N + f * F2N) * D4 + d4;
        float sx = 0.f, sy = 0.f, sz = 0.f, sw = 0.f;
#pragma unroll
        for (int k = 0; k < F2N; k++) {
            float4 v = p[(size_t)k * D4];
            sx += v.x; sy += v.y; sz += v.z; sw += v.w;
        }
        const float inv = 1.0f / (float)F2N;
        A14[((size_t)b * 11 + 1 + f) * (HH / 4) + D4 + d4] =
            make_float4(sx * inv, sy * inv, sz * inv, sw * inv);
    } else {
        int j = idx - HOP2_SLOTS;
        if (j >= BB * D4) return;
        int d4 = j & 31;
        int b = j >> 5;
        const float4* p = x4 + (size_t)b * NTOK * D4;
        // seed copy
        A14[(size_t)b * 11 * (HH / 4) + d4] = p[d4];
        // hop1 copy + mean(hop1)
        float sx = 0.f, sy = 0.f, sz = 0.f, sw = 0.f;
#pragma unroll
        for (int f = 0; f < F1N; f++) {
            float4 v = p[(size_t)(1 + f) * D4 + d4];
            A14[((size_t)b * 11 + 1 + f) * (HH / 4) + d4] = v;
            sx += v.x; sy += v.y; sz += v.z; sw += v.w;
        }
        const float inv = 1.0f / (float)F1N;
        A14[(size_t)b * 11 * (HH / 4) + D4 + d4] =
            make_float4(sx * inv, sy * inv, sz * inv, sw * inv);
    }
}

// ---------------- Tiled SGEMM with f32x2 FMAs + bias (+ optional ReLU) ----------------
// C[M,N] = act(A[M,K] @ W[K,N] + bias[N])
template <int BM, int BN, int BK, int TM, int TN, bool RELU>
__global__ __launch_bounds__((BM / TM) * (BN / TN))
void sgemm_bias(const float* __restrict__ A, const float* __restrict__ W,
                const float* __restrict__ bias, float* __restrict__ C,
                int M, int N, int K) {
    constexpr int NT = (BM / TM) * (BN / TN);
    __shared__ float As[BK][BM];  // transposed A tile
    __shared__ float Ws[BK][BN];

    const int tid = threadIdx.x;
    const int row0 = blockIdx.y * BM;
    const int col0 = blockIdx.x * BN;
    const int tx = tid % (BN / TN);
    const int ty = tid / (BN / TN);

    unsigned long long acc[TM][TN / 2];
#pragma unroll
    for (int i = 0; i < TM; i++)
#pragma unroll
        for (int j = 0; j < TN / 2; j++) acc[i][j] = 0ULL;

    for (int k0 = 0; k0 < K; k0 += BK) {
        // Load A tile (BM x BK), store transposed
#pragma unroll
        for (int i = tid; i < BM * BK / 4; i += NT) {
            int r = i / (BK / 4);
            int kk = (i % (BK / 4)) * 4;
            float4 v = *reinterpret_cast<const float4*>(
                &A[(size_t)(row0 + r) * K + k0 + kk]);
            As[kk + 0][r] = v.x;
            As[kk + 1][r] = v.y;
            As[kk + 2][r] = v.z;
            As[kk + 3][r] = v.w;
        }
        // Load W tile (BK x BN)
#pragma unroll
        for (int i = tid; i < BK * BN / 4; i += NT) {
            int kk = i / (BN / 4);
            int c = (i % (BN / 4)) * 4;
            *reinterpret_cast<float4*>(&Ws[kk][c]) =
                *reinterpret_cast<const float4*>(&W[(size_t)(k0 + kk) * N + col0 + c]);
        }
        __syncthreads();

#pragma unroll
        for (int kk = 0; kk < BK; kk++) {
            float a[TM];
            unsigned long long b2[TN / 2];
#pragma unroll
            for (int i = 0; i < TM; i += 4)
                *reinterpret_cast<float4*>(&a[i]) =
                    *reinterpret_cast<const float4*>(&As[kk][ty * TM + i]);
#pragma unroll
            for (int j = 0; j < TN / 2; j++)
                b2[j] = *reinterpret_cast<const unsigned long long*>(
                    &Ws[kk][tx * TN + 2 * j]);  // LDS.64: pre-packed pair
#pragma unroll
            for (int i = 0; i < TM; i++) {
                unsigned long long a2 = dup2(a[i]);
#pragma unroll
                for (int j = 0; j < TN / 2; j++) fma2(acc[i][j], a2, b2[j]);
            }
        }
        __syncthreads();
    }

    // Epilogue: bias (+ReLU), float2 stores
#pragma unroll
    for (int i = 0; i < TM; i++) {
        int r = row0 + ty * TM + i;
#pragma unroll
        for (int j = 0; j < TN / 2; j++) {
            float2 v = unpk2(acc[i][j]);
            int c = col0 + tx * TN + 2 * j;
            v.x += bias[c];
            v.y += bias[c + 1];
            if (RELU) {
                v.x = fmaxf(v.x, 0.0f);
                v.y = fmaxf(v.y, 0.0f);
            }
            *reinterpret_cast<float2*>(&C[(size_t)r * N + c]) = v;
        }
    }
}

// ---------------- K3: pool H1 -> A2 = [h0 | mean_f h1] ----------------
__global__ void k_pool() {
    int idx = blockIdx.x * blockDim.x + threadIdx.x;  // b*64 + c4
    if (idx >= BB * (HH / 4)) return;
    int c4 = idx & 63;
    int b = idx >> 6;
    const float4* H = reinterpret_cast<const float4*>(g_H1) + (size_t)b * 11 * (HH / 4);
    float4* A2 = reinterpret_cast<float4*>(g_A2);
    A2[(size_t)b * 128 + c4] = H[c4];  // h0 (already ReLU'd)
    float sx = 0.f, sy = 0.f, sz = 0.f, sw = 0.f;
#pragma unroll
    for (int f = 1; f <= F1N; f++) {
        float4 v = H[(size_t)f * (HH / 4) + c4];
        sx += v.x; sy += v.y; sz += v.z; sw += v.w;
    }
    const float inv = 1.0f / (float)F1N;
    A2[(size_t)b * 128 + 64 + c4] = make_float4(sx * inv, sy * inv, sz * inv, sw * inv);
}

// ---------------- launch ----------------
extern "C" void kernel_launch(void* const* d_in, const int* in_sizes, int n_in,
                              void* d_out, int out_size) {
    const float* x  = (const float*)d_in[0];
    const float* W1 = (const float*)d_in[1];
    const float* b1 = (const float*)d_in[2];
    const float* W2 = (const float*)d_in[3];
    const float* b2 = (const float*)d_in[4];
    float* out = (float*)d_out;

    float *a1, *h1, *a2;
    cudaGetSymbolAddress((void**)&a1, g_A1);
    cudaGetSymbolAddress((void**)&h1, g_H1);
    cudaGetSymbolAddress((void**)&a2, g_A2);

    // K1: reduction (655360 hop2 slots + 65536 seed/hop1 slots)
    {
        int total = BB * F1N * D4 + BB * D4;  // 720896
        k_reduce<<<(total + 255) / 256, 256>>>(reinterpret_cast<const float4*>(x));
    }
    // K2: H1 = relu(A1 @ W1 + b1), M=22528 N=256 K=256
    sgemm_bias<128, 128, 16, 8, 8, true>
        <<<dim3(HH / 128, MROWS / 128), 256>>>(a1, W1, b1, h1, MROWS, HH, 2 * DD);
    // K3: pool
    k_pool<<<(BB * (HH / 4) + 255) / 256, 256>>>();
    // K4: out = A2 @ W2 + b2, M=2048 N=256 K=512
    sgemm_bias<64, 64, 32, 4, 4, false>
        <<<dim3(HH / 64, BB / 64), 256>>>(a2, W2, b2, out, BB, HH, 2 * HH);
}

// round 3
// speedup vs baseline: 1.8013x; 1.8013x over previous
#include <cuda_runtime.h>
#include <cuda_bf16.h>
#include <cstdint>

// ---------------- problem constants ----------------
#define BB    2048
#define F1N   10
#define F2N   25
#define NTOK  261
#define D4    32
#define MROWS (BB * 11)   // 22528

// ---------------- scratch (device globals, allocation-free) ----------------
__device__ __align__(16) __nv_bfloat16 g_Ah[MROWS * 256];
__device__ __align__(16) __nv_bfloat16 g_Al[MROWS * 256];
__device__ __align__(16) float         g_H1[MROWS * 256];
__device__ __align__(16) __nv_bfloat16 g_A2h[BB * 512];
__device__ __align__(16) __nv_bfloat16 g_A2l[BB * 512];
__device__ __align__(16) __nv_bfloat16 g_W1hT[256 * 256];
__device__ __align__(16) __nv_bfloat16 g_W1lT[256 * 256];
__device__ __align__(16) __nv_bfloat16 g_W2hT[256 * 512];
__device__ __align__(16) __nv_bfloat16 g_W2lT[256 * 512];

// ---------------- PTX helpers (base sm_100-safe: no tcgen05) ----------------
__device__ __forceinline__ uint32_t smem_u32(const void* p) {
    uint32_t a;
    asm("{ .reg .u64 t; cvta.to.shared.u64 t, %1; cvt.u32.u64 %0, t; }" : "=r"(a) : "l"(p));
    return a;
}
__device__ __forceinline__ void cp16(uint32_t s, const void* g) {
    asm volatile("cp.async.cg.shared.global [%0], [%1], 16;" :: "r"(s), "l"(g));
}
#define CP_COMMIT() asm volatile("cp.async.commit_group;" ::: "memory")
#define CP_WAIT(n)  asm volatile("cp.async.wait_group %0;" :: "n"(n) : "memory")

__device__ __forceinline__ void ldsm4(uint32_t* r, uint32_t addr) {
    asm volatile("ldmatrix.sync.aligned.m8n8.x4.shared.b16 {%0,%1,%2,%3}, [%4];"
                 : "=r"(r[0]), "=r"(r[1]), "=r"(r[2]), "=r"(r[3]) : "r"(addr));
}
__device__ __forceinline__ void mma16816(float* c, const uint32_t* a, const uint32_t* b) {
    asm volatile(
        "mma.sync.aligned.m16n8k16.row.col.f32.bf16.bf16.f32 "
        "{%0,%1,%2,%3}, {%4,%5,%6,%7}, {%8,%9}, {%0,%1,%2,%3};"
        : "+f"(c[0]), "+f"(c[1]), "+f"(c[2]), "+f"(c[3])
        : "r"(a[0]), "r"(a[1]), "r"(a[2]), "r"(a[3]), "r"(b[0]), "r"(b[1]));
}

// ---------------- bf16 split helpers ----------------
__device__ __forceinline__ void split1(float w, unsigned short& h, unsigned short& l) {
    __nv_bfloat16 hb = __float2bfloat16_rn(w);
    float r = w - __bfloat162float(hb);
    __nv_bfloat16 lb = __float2bfloat16_rn(r);
    h = __bfloat16_as_ushort(hb);
    l = __bfloat16_as_ushort(lb);
}
__device__ __forceinline__ void split_store4(__nv_bfloat16* H, __nv_bfloat16* L,
                                             size_t idx, float4 v) {
    unsigned short hs[4], ls[4];
    float f[4] = {v.x, v.y, v.z, v.w};
#pragma unroll
    for (int i = 0; i < 4; i++) split1(f[i], hs[i], ls[i]);
    uint2 hv = make_uint2((uint32_t)hs[0] | ((uint32_t)hs[1] << 16),
                          (uint32_t)hs[2] | ((uint32_t)hs[3] << 16));
    uint2 lv = make_uint2((uint32_t)ls[0] | ((uint32_t)ls[1] << 16),
                          (uint32_t)ls[2] | ((uint32_t)ls[3] << 16));
    *reinterpret_cast<uint2*>(H + idx) = hv;
    *reinterpret_cast<uint2*>(L + idx) = lv;
}

// ---------------- K0: weight transpose + split ----------------
__global__ void k_convw(const float* __restrict__ W1, const float* __restrict__ W2) {
    int i = blockIdx.x * blockDim.x + threadIdx.x;
    if (i < 256 * 256) {
        int n = i >> 8, k = i & 255;
        unsigned short h, l;
        split1(W1[k * 256 + n], h, l);
        g_W1hT[n * 256 + k] = __ushort_as_bfloat16(h);
        g_W1lT[n * 256 + k] = __ushort_as_bfloat16(l);
    } else {
        int j = i - 256 * 256;
        if (j >= 256 * 512) return;
        int n = j >> 9, k = j & 511;
        unsigned short h, l;
        split1(W2[k * 256 + n], h, l);
        g_W2hT[n * 512 + k] = __ushort_as_bfloat16(h);
        g_W2lT[n * 512 + k] = __ushort_as_bfloat16(l);
    }
}

// ---------------- K1: neighbor means -> split bf16 A rows ----------------
__global__ void k_reduce(const float4* __restrict__ x4) {
    const int HOP2_SLOTS = BB * F1N * D4;
    int idx = blockIdx.x * blockDim.x + threadIdx.x;
    if (idx < HOP2_SLOTS) {
        int d4 = idx & 31;
        int fg = idx >> 5;
        int f = fg % F1N;
        int b = fg / F1N;
        const float4* p = x4 + (size_t)b * NTOK * D4 + (size_t)(1 + F1N + f * F2N) * D4 + d4;
        float sx = 0.f, sy = 0.f, sz = 0.f, sw = 0.f;
#pragma unroll
        for (int k = 0; k < F2N; k++) {
            float4 v = p[(size_t)k * D4];
            sx += v.x; sy += v.y; sz += v.z; sw += v.w;
        }
        const float inv = 1.0f / (float)F2N;
        size_t row = (size_t)b * 11 + 1 + f;
        split_store4(g_Ah, g_Al, row * 256 + 128 + d4 * 4,
                     make_float4(sx * inv, sy * inv, sz * inv, sw * inv));
    } else {
        int j = idx - HOP2_SLOTS;
        if (j >= BB * D4) return;
        int d4 = j & 31;
        int b = j >> 5;
        const float4* p = x4 + (size_t)b * NTOK * D4;
        size_t base = (size_t)b * 11;
        split_store4(g_Ah, g_Al, base * 256 + d4 * 4, p[d4]);  // seed
        float sx = 0.f, sy = 0.f, sz = 0.f, sw = 0.f;
#pragma unroll
        for (int f = 0; f < F1N; f++) {
            float4 v = p[(size_t)(1 + f) * D4 + d4];
            split_store4(g_Ah, g_Al, (base + 1 + f) * 256 + d4 * 4, v);
            sx += v.x; sy += v.y; sz += v.z; sw += v.w;
        }
        const float inv = 1.0f / (float)F1N;
        split_store4(g_Ah, g_Al, base * 256 + 128 + d4 * 4,
                     make_float4(sx * inv, sy * inv, sz * inv, sw * inv));
    }
}

// ---------------- warp-MMA GEMM: C[M,256] = act(A[M,K] @ W[K,256] + bias) ----------------
// A split (Ah/Al [M][K] bf16 row-major), W pre-transposed+split ([n][K] bf16).
// 3-term: AhBh + AhBl + AlBh, fp32 accum. 2-stage cp.async pipeline, K chunks of 64.
template <int BM, int BN, int KTOT, int WM, int WN, bool RELU>
__global__ __launch_bounds__(256)
void gemm_mma(const __nv_bfloat16* __restrict__ Ah_g, const __nv_bfloat16* __restrict__ Al_g,
              const __nv_bfloat16* __restrict__ Bh_g, const __nv_bfloat16* __restrict__ Bl_g,
              const float* __restrict__ bias, float* __restrict__ C) {
    constexpr int NCH = KTOT / 64;
    constexpr int SA = BM * 128;        // bytes per A buffer (row = 64 bf16 = 128B)
    constexpr int SB = BN * 128;
    constexpr int STAGE = 2 * SA + 2 * SB;
    constexpr int NWN = BN / WN;        // warps along N
    constexpr int MT = WM / 16;         // m16 tiles per warp
    constexpr int NT8 = WN / 8;         // n8 tiles per warp
    constexpr int NT16 = WN / 16;       // n16 ldmatrix groups per warp

    extern __shared__ char smem[];
    const uint32_t sb = smem_u32(smem);
    const int tid = threadIdx.x, wid = tid >> 5, lane = tid & 31;
    const int row0 = blockIdx.x * BM, col0 = blockIdx.y * BN;
    const int wm = (wid / NWN) * WM;
    const int wn = (wid % NWN) * WN;

    float acc[MT][NT8][4];
#pragma unroll
    for (int mi = 0; mi < MT; mi++)
#pragma unroll
        for (int j = 0; j < NT8; j++)
#pragma unroll
            for (int q = 0; q < 4; q++) acc[mi][j][q] = 0.f;

    auto load_stage = [&](int c, int s) {
        const int kofs = c * 64;
        const uint32_t base = sb + s * STAGE;
#pragma unroll
        for (int i = tid; i < BM * 8; i += 256) {
            int r = i >> 3, cc = i & 7;
            uint32_t sw = r * 128 + ((cc ^ (r & 7)) << 4);
            size_t go = (size_t)(row0 + r) * KTOT + kofs + cc * 8;
            cp16(base + sw, Ah_g + go);
            cp16(base + SA + sw, Al_g + go);
        }
#pragma unroll
        for (int i = tid; i < BN * 8; i += 256) {
            int r = i >> 3, cc = i & 7;
            uint32_t sw = r * 128 + ((cc ^ (r & 7)) << 4);
            size_t go = (size_t)(col0 + r) * KTOT + kofs + cc * 8;
            cp16(base + 2 * SA + sw, Bh_g + go);
            cp16(base + 2 * SA + SB + sw, Bl_g + go);
        }
    };

    load_stage(0, 0);
    CP_COMMIT();

    for (int c = 0; c < NCH; c++) {
        const int s = c & 1;
        if (c + 1 < NCH) {
            load_stage(c + 1, s ^ 1);
            CP_COMMIT();
            CP_WAIT(1);
        } else {
            CP_WAIT(0);
        }
        __syncthreads();
        const uint32_t base = sb + s * STAGE;

#pragma unroll
        for (int k16 = 0; k16 < 4; k16++) {
            const int cc = k16 * 2 + (lane >> 4);  // 16B chunk index for this lane
            uint32_t ah[MT][4], al[MT][4], bh[NT16][4], bl[NT16][4];
#pragma unroll
            for (int mi = 0; mi < MT; mi++) {
                int r = wm + mi * 16 + (lane & 15);
                uint32_t ad = base + r * 128 + ((cc ^ (r & 7)) << 4);
                ldsm4(ah[mi], ad);
                ldsm4(al[mi], ad + SA);
            }
#pragma unroll
            for (int ni = 0; ni < NT16; ni++) {
                int r = wn + ni * 16 + (lane & 15);
                uint32_t ad = base + 2 * SA + r * 128 + ((cc ^ (r & 7)) << 4);
                ldsm4(bh[ni], ad);
                ldsm4(bl[ni], ad + SB);
            }
#pragma unroll
            for (int mi = 0; mi < MT; mi++)
#pragma unroll
                for (int j = 0; j < NT8; j++) {
                    uint32_t bfh[2] = {bh[j >> 1][j & 1], bh[j >> 1][(j & 1) + 2]};
                    uint32_t bfl[2] = {bl[j >> 1][j & 1], bl[j >> 1][(j & 1) + 2]};
                    mma16816(acc[mi][j], ah[mi], bfh);   // Ah*Bh
                    mma16816(acc[mi][j], ah[mi], bfl);   // Ah*Bl
                    mma16816(acc[mi][j], al[mi], bfh);   // Al*Bh
                }
        }
        __syncthreads();
    }

    // epilogue: bias (+ReLU), float2 stores
    const int g = lane >> 2, q = lane & 3;
#pragma unroll
    for (int mi = 0; mi < MT; mi++)
#pragma unroll
        for (int j = 0; j < NT8; j++) {
            int ccol = col0 + wn + j * 8 + 2 * q;
            float bx = __ldg(bias + ccol), by = __ldg(bias + ccol + 1);
            int r0 = row0 + wm + mi * 16 + g;
            float2 v0 = make_float2(acc[mi][j][0] + bx, acc[mi][j][1] + by);
            float2 v1 = make_float2(acc[mi][j][2] + bx, acc[mi][j][3] + by);
            if (RELU) {
                v0.x = fmaxf(v0.x, 0.f); v0.y = fmaxf(v0.y, 0.f);
                v1.x = fmaxf(v1.x, 0.f); v1.y = fmaxf(v1.y, 0.f);
            }
            *reinterpret_cast<float2*>(&C[(size_t)r0 * 256 + ccol]) = v0;
            *reinterpret_cast<float2*>(&C[(size_t)(r0 + 8) * 256 + ccol]) = v1;
        }
}

// ---------------- K3: pool H1 -> split A2 = [h0 | mean_f h1] ----------------
__global__ void k_pool() {
    int idx = blockIdx.x * blockDim.x + threadIdx.x;
    if (idx >= BB * 64) return;
    int c4 = idx & 63;
    int b = idx >> 6;
    const float4* H = reinterpret_cast<const float4*>(g_H1) + (size_t)b * 11 * 64;
    split_store4(g_A2h, g_A2l, (size_t)b * 512 + c4 * 4, H[c4]);  // h0
    float sx = 0.f, sy = 0.f, sz = 0.f, sw = 0.f;
#pragma unroll
    for (int f = 1; f <= F1N; f++) {
        float4 v = H[(size_t)f * 64 + c4];
        sx += v.x; sy += v.y; sz += v.z; sw += v.w;
    }
    const float inv = 1.0f / (float)F1N;
    split_store4(g_A2h, g_A2l, (size_t)b * 512 + 256 + c4 * 4,
                 make_float4(sx * inv, sy * inv, sz * inv, sw * inv));
}

// ---------------- launch ----------------
static constexpr int SMEM1 = 2 * (2 * 64 * 128 + 2 * 128 * 128);  // 98304
static constexpr int SMEM2 = 2 * (2 * 64 * 128 + 2 * 64 * 128);   // 65536

extern "C" void kernel_launch(void* const* d_in, const int* in_sizes, int n_in,
                              void* d_out, int out_size) {
    const float* x  = (const float*)d_in[0];
    const float* W1 = (const float*)d_in[1];
    const float* b1 = (const float*)d_in[2];
    const float* W2 = (const float*)d_in[3];
    const float* b2 = (const float*)d_in[4];
    float* out = (float*)d_out;

    __nv_bfloat16 *ah, *al, *a2h, *a2l, *w1h, *w1l, *w2h, *w2l;
    float* h1;
    cudaGetSymbolAddress((void**)&ah,  g_Ah);
    cudaGetSymbolAddress((void**)&al,  g_Al);
    cudaGetSymbolAddress((void**)&h1,  g_H1);
    cudaGetSymbolAddress((void**)&a2h, g_A2h);
    cudaGetSymbolAddress((void**)&a2l, g_A2l);
    cudaGetSymbolAddress((void**)&w1h, g_W1hT);
    cudaGetSymbolAddress((void**)&w1l, g_W1lT);
    cudaGetSymbolAddress((void**)&w2h, g_W2hT);
    cudaGetSymbolAddress((void**)&w2l, g_W2lT);

    cudaFuncSetAttribute((const void*)gemm_mma<64, 128, 256, 32, 32, true>,
                         cudaFuncAttributeMaxDynamicSharedMemorySize, SMEM1);
    cudaFuncSetAttribute((const void*)gemm_mma<64, 64, 512, 32, 16, false>,
                         cudaFuncAttributeMaxDynamicSharedMemorySize, SMEM2);

    // K0: weight split/transpose
    k_convw<<<(256 * 256 + 256 * 512 + 255) / 256, 256>>>(W1, W2);
    // K1: neighbor means + input split
    {
        int total = BB * F1N * D4 + BB * D4;
        k_reduce<<<(total + 255) / 256, 256>>>(reinterpret_cast<const float4*>(x));
    }
    // GEMM1: H1 = relu(A @ W1 + b1), M=22528, K=256, grid 352x2
    gemm_mma<64, 128, 256, 32, 32, true>
        <<<dim3(MROWS / 64, 2), 256, SMEM1>>>(ah, al, w1h, w1l, b1, h1);
    // K3: pool
    k_pool<<<(BB * 64 + 255) / 256, 256>>>();
    // GEMM2: out = A2 @ W2 + b2, M=2048, K=512, grid 32x4
    gemm_mma<64, 64, 512, 32, 16, false>
        <<<dim3(BB / 64, 4), 256, SMEM2>>>(a2h, a2l, w2h, w2l, b2, out);
}